// round 6
// baseline (speedup 1.0000x reference)
#include <cuda_runtime.h>
#include <cuda_fp16.h>
#include <cuda_bf16.h>
#include <cstdint>

// ---------------------------------------------------------------------------
// Problem constants
// ---------------------------------------------------------------------------
constexpr int IN_F    = 4096;    // K
constexpr int OUT_F   = 4096;    // N
constexpr int M_TOTAL = 8192;    // M

// GEMM tiling
constexpr int BM = 128, BN = 256, BK = 64;
constexpr int STAGES = 3;
constexpr int NSTG   = IN_F / BK;        // 64
constexpr int LDR    = 72;               // smem row stride in halfs (144B)
constexpr int A_BYTES     = BM * LDR * 2;            // 18432
constexpr int B_BYTES     = BN * LDR * 2;            // 36864
constexpr int STAGE_BYTES = A_BYTES + B_BYTES;       // 55296
constexpr int SMEM_TOTAL  = STAGES * STAGE_BYTES;    // 165888

// Scratch (__device__ globals = allowed scratch)
__device__ __half g_X [(size_t)M_TOTAL * IN_F];   // canonical fp16 x  (64MB)
__device__ __half g_Wt[(size_t)OUT_F * IN_F];     // dequant W^T [N,K] (32MB)
__device__ int    g_mode;                         // 0=f32, 1=fp16, 2=bf16 buffers

// ---------------------------------------------------------------------------
// helpers
// ---------------------------------------------------------------------------
__device__ __forceinline__ float dec_h(unsigned short v) {
    __half_raw h; h.x = v; return __half2float(__half(h));
}
__device__ __forceinline__ float dec_b(unsigned short v) {
    __nv_bfloat16_raw r; r.x = v; return __bfloat162float(__nv_bfloat16(r));
}
__device__ __forceinline__ unsigned short enc_h(float f) {
    __half h = __float2half(f); return reinterpret_cast<unsigned short&>(h);
}
__device__ __forceinline__ unsigned short enc_b(float f) {
    __nv_bfloat16 b = __float2bfloat16(f); return reinterpret_cast<unsigned short&>(b);
}
__device__ __forceinline__ void cp16(uint32_t saddr, const void* g) {
    asm volatile("cp.async.cg.shared.global [%0], [%1], 16;\n" :: "r"(saddr), "l"(g));
}
__device__ __forceinline__ void cp_commit() {
    asm volatile("cp.async.commit_group;\n" ::: "memory");
}
template <int N>
__device__ __forceinline__ void cp_wait() {
    asm volatile("cp.async.wait_group %0;\n" :: "n"(N) : "memory");
}
__device__ __forceinline__ void ldsm4(uint32_t* r, uint32_t addr) {
    asm volatile("ldmatrix.sync.aligned.m8n8.x4.shared.b16 {%0,%1,%2,%3}, [%4];\n"
                 : "=r"(r[0]), "=r"(r[1]), "=r"(r[2]), "=r"(r[3]) : "r"(addr));
}
__device__ __forceinline__ void mma16816(float* c, const uint32_t* a,
                                         uint32_t b0, uint32_t b1) {
    asm volatile(
        "mma.sync.aligned.m16n8k16.row.col.f32.f16.f16.f32 "
        "{%0,%1,%2,%3}, {%4,%5,%6,%7}, {%8,%9}, {%0,%1,%2,%3};\n"
        : "+f"(c[0]), "+f"(c[1]), "+f"(c[2]), "+f"(c[3])
        : "r"(a[0]), "r"(a[1]), "r"(a[2]), "r"(a[3]), "r"(b0), "r"(b1));
}

// ---------------------------------------------------------------------------
// Kernel 0: dtype probe on scales (true values in (0.001, 0.011]).
// ---------------------------------------------------------------------------
__global__ void detect_kernel(const void* scales) {
    const unsigned short* su = (const unsigned short*)scales;
    int c16 = 0, cbf = 0;
    for (int i = 0; i < 64; i++) {
        float vh = dec_h(su[i]); if (vh > 0.0005f && vh < 0.02f) c16++;
        float vb = dec_b(su[i]); if (vb > 0.0005f && vb < 0.02f) cbf++;
    }
    g_mode = (c16 >= 48) ? 1 : ((cbf >= 48) ? 2 : 0);
}

// ---------------------------------------------------------------------------
// Kernel 1: canonicalize x -> fp16 g_X (8 elems/thread)
// ---------------------------------------------------------------------------
__global__ void convert_x_kernel(const void* __restrict__ x_raw) {
    const int mode = g_mode;
    const size_t i8 = (size_t)blockIdx.x * blockDim.x + threadIdx.x;
    __half out[8];
    if (mode == 0) {
        const float4* xf = (const float4*)x_raw;
        const float4 a = xf[i8 * 2 + 0];
        const float4 b = xf[i8 * 2 + 1];
        out[0] = __float2half(a.x); out[1] = __float2half(a.y);
        out[2] = __float2half(a.z); out[3] = __float2half(a.w);
        out[4] = __float2half(b.x); out[5] = __float2half(b.y);
        out[6] = __float2half(b.z); out[7] = __float2half(b.w);
    } else {
        const uint4 v = ((const uint4*)x_raw)[i8];
        const unsigned int w[4] = {v.x, v.y, v.z, v.w};
        if (mode == 1) {
            *reinterpret_cast<uint4*>(out) = v;
        } else {
#pragma unroll
            for (int k = 0; k < 4; k++) {
                out[2*k+0] = __float2half(dec_b((unsigned short)(w[k] & 0xFFFF)));
                out[2*k+1] = __float2half(dec_b((unsigned short)(w[k] >> 16)));
            }
        }
    }
    *reinterpret_cast<uint4*>(&g_X[i8 * 8]) = *reinterpret_cast<const uint4*>(out);
}

// ---------------------------------------------------------------------------
// Kernel 2: dequantize 4-bit weights -> fp16 W^T [N, K] (K-major, coalesced)
// ---------------------------------------------------------------------------
__global__ void dequant_kernel(const int32_t* __restrict__ qweight,
                               const int32_t* __restrict__ qzeros,
                               const void* __restrict__ scales_raw) {
    const int mode = g_mode;
    const int tx = threadIdx.x;                  // 0..31
    const int ty = threadIdx.y;                  // 0..7
    const int j  = blockIdx.x * 8 + ty;          // N index
    const int i8 = blockIdx.y * 32 + tx;         // K/8 index
    const int g  = i8 >> 4;

    const uint32_t q = (uint32_t)qweight[(size_t)i8 * OUT_F + j];
    const int z = ((uint32_t)qzeros[(size_t)g * (OUT_F >> 3) + (j >> 3)] >> ((j & 7) << 2)) & 0xF;

    float s;
    if (mode == 0)      s = ((const float*)scales_raw)[(size_t)g * OUT_F + j];
    else if (mode == 1) s = dec_h(((const unsigned short*)scales_raw)[(size_t)g * OUT_F + j]);
    else                s = dec_b(((const unsigned short*)scales_raw)[(size_t)g * OUT_F + j]);
    const float zs = s * (float)z;

    __half out8[8];
#pragma unroll
    for (int r = 0; r < 8; r++) {
        const int w = (q >> (r << 2)) & 0xF;
        out8[r] = __float2half(s * (float)w - zs);
    }
    *reinterpret_cast<uint4*>(&g_Wt[(size_t)j * IN_F + i8 * 8]) =
        *reinterpret_cast<const uint4*>(out8);
}

// ---------------------------------------------------------------------------
// Kernel 3: GEMM via mma.sync.m16n8k16 + ldmatrix + 3-stage cp.async,
// with per-kk fragment double-buffering and hoisted cp.async addressing.
// CTA 128x256x64, 8 warps (2x4), warp tile 64x64.
// ---------------------------------------------------------------------------
__global__ void __launch_bounds__(256, 1)
gemm_kernel(const void* __restrict__ bias_raw, void* __restrict__ out_raw) {
    extern __shared__ __align__(128) unsigned char smem[];
    const uint32_t sbase = (uint32_t)__cvta_generic_to_shared(smem);

    const int tid  = threadIdx.x;
    const int wid  = tid >> 5;
    const int lane = tid & 31;
    const int wm   = wid >> 2;            // 0..1
    const int wn   = wid & 3;             // 0..3
    const int mode = g_mode;

    const int m0 = blockIdx.x * BM;
    const int n0 = blockIdx.y * BN;

    // ---- hoisted cp.async addressing (per-thread, computed once) ----
    // A: 4 chunks/thread, B: 8 chunks/thread. Global ptrs advance by BK/stage.
    const __half* gA[4];
    const __half* gB[8];
    uint32_t sAo[4], sBo[8];
#pragma unroll
    for (int t = 0; t < 4; t++) {
        const int idx = tid + t * 256;
        const int row = idx >> 3, seg = idx & 7;
        gA[t]  = g_X + (size_t)(m0 + row) * IN_F + seg * 8;
        sAo[t] = (uint32_t)(row * (LDR * 2) + seg * 16);
    }
#pragma unroll
    for (int t = 0; t < 8; t++) {
        const int idx = tid + t * 256;
        const int row = idx >> 3, seg = idx & 7;
        gB[t]  = g_Wt + (size_t)(n0 + row) * IN_F + seg * 8;
        sBo[t] = (uint32_t)(A_BYTES + row * (LDR * 2) + seg * 16);
    }

    // ldmatrix per-lane base offsets (within a stage)
    const int l15  = lane & 15;
    const int lsel = (lane >> 4) * 16;
    const uint32_t a_off = (uint32_t)(wm * 64 + l15) * (LDR * 2) + lsel;
    const uint32_t b_off = (uint32_t)A_BYTES + (uint32_t)(wn * 64 + l15) * (LDR * 2) + lsel;

    float acc[4][8][4];
#pragma unroll
    for (int i = 0; i < 4; i++)
#pragma unroll
        for (int j = 0; j < 8; j++)
#pragma unroll
            for (int k = 0; k < 4; k++) acc[i][j][k] = 0.0f;

    // stage loader: issues 12 cp16s into buffer `buf`, advances global ptrs
#define LOAD_STAGE(buf_)                                                     \
    do {                                                                     \
        const uint32_t sb_ = sbase + (buf_) * STAGE_BYTES;                   \
        _Pragma("unroll")                                                    \
        for (int t = 0; t < 4; t++) { cp16(sb_ + sAo[t], gA[t]); gA[t] += BK; } \
        _Pragma("unroll")                                                    \
        for (int t = 0; t < 8; t++) { cp16(sb_ + sBo[t], gB[t]); gB[t] += BK; } \
        cp_commit();                                                         \
    } while (0)

    // prologue: stages 0,1
    LOAD_STAGE(0);
    LOAD_STAGE(1);

    uint32_t af[2][4][4], bf[2][4][4];

    for (int i = 0; i < NSTG; i++) {
        const int buf = i % STAGES;
        if (i == NSTG - 1) cp_wait<0>(); else cp_wait<1>();
        __syncthreads();

        const int ls = i + STAGES - 1;
        if (ls < NSTG) LOAD_STAGE(ls % STAGES);

        const uint32_t st = sbase + buf * STAGE_BYTES;

        // preload kk=0 fragments
#pragma unroll
        for (int mi = 0; mi < 4; mi++)
            ldsm4(af[0][mi], st + a_off + mi * (16 * LDR * 2));
#pragma unroll
        for (int nj = 0; nj < 4; nj++)
            ldsm4(bf[0][nj], st + b_off + nj * (16 * LDR * 2));

#pragma unroll
        for (int kk = 0; kk < BK / 16; kk++) {
            const int cur = kk & 1, nxt = cur ^ 1;
            if (kk < BK / 16 - 1) {
#pragma unroll
                for (int mi = 0; mi < 4; mi++)
                    ldsm4(af[nxt][mi], st + a_off + mi * (16 * LDR * 2) + (kk + 1) * 32);
#pragma unroll
                for (int nj = 0; nj < 4; nj++)
                    ldsm4(bf[nxt][nj], st + b_off + nj * (16 * LDR * 2) + (kk + 1) * 32);
            }
#pragma unroll
            for (int mi = 0; mi < 4; mi++)
#pragma unroll
                for (int nj = 0; nj < 4; nj++) {
                    mma16816(acc[mi][nj * 2 + 0], af[cur][mi], bf[cur][nj][0], bf[cur][nj][2]);
                    mma16816(acc[mi][nj * 2 + 1], af[cur][mi], bf[cur][nj][1], bf[cur][nj][3]);
                }
        }
    }
#undef LOAD_STAGE

    // ---- epilogue: direct register -> global with fused bias ----
    const int mrow = m0 + wm * 64 + (lane >> 2);
    const int ncol = n0 + wn * 64 + (lane & 3) * 2;

    float bl[8], bh[8];
#pragma unroll
    for (int j = 0; j < 8; j++) {
        const int c = ncol + j * 8;
        if (mode == 0) {
            bl[j] = ((const float*)bias_raw)[c];
            bh[j] = ((const float*)bias_raw)[c + 1];
        } else if (mode == 1) {
            bl[j] = dec_h(((const unsigned short*)bias_raw)[c]);
            bh[j] = dec_h(((const unsigned short*)bias_raw)[c + 1]);
        } else {
            bl[j] = dec_b(((const unsigned short*)bias_raw)[c]);
            bh[j] = dec_b(((const unsigned short*)bias_raw)[c + 1]);
        }
    }

#pragma unroll
    for (int mi = 0; mi < 4; mi++) {
        const int r0 = mrow + mi * 16;
#pragma unroll
        for (int j = 0; j < 8; j++) {
            const int c = ncol + j * 8;
            const float v0 = acc[mi][j][0] + bl[j];
            const float v1 = acc[mi][j][1] + bh[j];
            const float v2 = acc[mi][j][2] + bl[j];
            const float v3 = acc[mi][j][3] + bh[j];
            if (mode == 0) {
                float2 p0, p1;
                p0.x = __half2float(__float2half(v0));
                p0.y = __half2float(__float2half(v1));
                p1.x = __half2float(__float2half(v2));
                p1.y = __half2float(__float2half(v3));
                *reinterpret_cast<float2*>((float*)out_raw + (size_t)r0 * OUT_F + c) = p0;
                *reinterpret_cast<float2*>((float*)out_raw + (size_t)(r0 + 8) * OUT_F + c) = p1;
            } else if (mode == 1) {
                uint32_t p0 = (uint32_t)enc_h(v0) | ((uint32_t)enc_h(v1) << 16);
                uint32_t p1 = (uint32_t)enc_h(v2) | ((uint32_t)enc_h(v3) << 16);
                *reinterpret_cast<uint32_t*>((unsigned short*)out_raw + (size_t)r0 * OUT_F + c) = p0;
                *reinterpret_cast<uint32_t*>((unsigned short*)out_raw + (size_t)(r0 + 8) * OUT_F + c) = p1;
            } else {
                uint32_t p0 = (uint32_t)enc_b(v0) | ((uint32_t)enc_b(v1) << 16);
                uint32_t p1 = (uint32_t)enc_b(v2) | ((uint32_t)enc_b(v3) << 16);
                *reinterpret_cast<uint32_t*>((unsigned short*)out_raw + (size_t)r0 * OUT_F + c) = p0;
                *reinterpret_cast<uint32_t*>((unsigned short*)out_raw + (size_t)(r0 + 8) * OUT_F + c) = p1;
            }
        }
    }
}

// ---------------------------------------------------------------------------
// Launch
// ---------------------------------------------------------------------------
extern "C" void kernel_launch(void* const* d_in, const int* in_sizes, int n_in,
                              void* d_out, int out_size) {
    const void*    x       = d_in[0];
    const int32_t* qweight = (const int32_t*)d_in[1];
    const int32_t* qzeros  = (const int32_t*)d_in[2];
    const void*    scales  = d_in[3];
    const void*    bias    = d_in[4];

    detect_kernel<<<1, 1>>>(scales);

    const unsigned nchunks = (unsigned)((size_t)M_TOTAL * IN_F / 8);
    convert_x_kernel<<<nchunks / 256, 256>>>(x);

    dequant_kernel<<<dim3(OUT_F / 8, IN_F / 256), dim3(32, 8)>>>(qweight, qzeros, scales);

    cudaFuncSetAttribute(gemm_kernel,
                         cudaFuncAttributeMaxDynamicSharedMemorySize, SMEM_TOTAL);
    dim3 grid(M_TOTAL / BM, OUT_F / BN);    // (64, 16)
    gemm_kernel<<<grid, 256, SMEM_TOTAL>>>(bias, d_out);
}

// round 7
// speedup vs baseline: 1.0211x; 1.0211x over previous
#include <cuda_runtime.h>
#include <cuda_fp16.h>
#include <cuda_bf16.h>
#include <cstdint>

// ---------------------------------------------------------------------------
// Problem constants
// ---------------------------------------------------------------------------
constexpr int IN_F    = 4096;    // K
constexpr int OUT_F   = 4096;    // N
constexpr int M_TOTAL = 8192;    // M

// GEMM tiling: CTA 128x128x64, 8 warps (2x4), warp tile 64x32, 2 CTAs/SM
constexpr int BM = 128, BN = 128, BK = 64;
constexpr int STAGES = 3;
constexpr int NSTG   = IN_F / BK;        // 64
constexpr int LDR    = 72;               // smem row stride in halfs (144B)
constexpr int LDR2   = LDR * 2;          // bytes
constexpr int A_BYTES     = BM * LDR2;               // 18432
constexpr int B_BYTES     = BN * LDR2;               // 18432
constexpr int STAGE_BYTES = A_BYTES + B_BYTES;       // 36864
constexpr int SMEM_TOTAL  = STAGES * STAGE_BYTES;    // 110592

// Scratch (__device__ globals = allowed scratch)
__device__ __half g_X [(size_t)M_TOTAL * IN_F];   // canonical fp16 x  (64MB)
__device__ __half g_Wt[(size_t)OUT_F * IN_F];     // dequant W^T [N,K] (32MB)
__device__ int    g_mode;                         // 0=f32, 1=fp16, 2=bf16 buffers

// ---------------------------------------------------------------------------
// helpers
// ---------------------------------------------------------------------------
__device__ __forceinline__ float dec_h(unsigned short v) {
    __half_raw h; h.x = v; return __half2float(__half(h));
}
__device__ __forceinline__ float dec_b(unsigned short v) {
    __nv_bfloat16_raw r; r.x = v; return __bfloat162float(__nv_bfloat16(r));
}
__device__ __forceinline__ unsigned short enc_h(float f) {
    __half h = __float2half(f); return reinterpret_cast<unsigned short&>(h);
}
__device__ __forceinline__ unsigned short enc_b(float f) {
    __nv_bfloat16 b = __float2bfloat16(f); return reinterpret_cast<unsigned short&>(b);
}
__device__ __forceinline__ void cp16(uint32_t saddr, const void* g) {
    asm volatile("cp.async.cg.shared.global [%0], [%1], 16;\n" :: "r"(saddr), "l"(g));
}
__device__ __forceinline__ void cp_commit() {
    asm volatile("cp.async.commit_group;\n" ::: "memory");
}
template <int N>
__device__ __forceinline__ void cp_wait() {
    asm volatile("cp.async.wait_group %0;\n" :: "n"(N) : "memory");
}
__device__ __forceinline__ void ldsm4(uint32_t* r, uint32_t addr) {
    asm volatile("ldmatrix.sync.aligned.m8n8.x4.shared.b16 {%0,%1,%2,%3}, [%4];\n"
                 : "=r"(r[0]), "=r"(r[1]), "=r"(r[2]), "=r"(r[3]) : "r"(addr));
}
__device__ __forceinline__ void mma16816(float* c, const uint32_t* a,
                                         uint32_t b0, uint32_t b1) {
    asm volatile(
        "mma.sync.aligned.m16n8k16.row.col.f32.f16.f16.f32 "
        "{%0,%1,%2,%3}, {%4,%5,%6,%7}, {%8,%9}, {%0,%1,%2,%3};\n"
        : "+f"(c[0]), "+f"(c[1]), "+f"(c[2]), "+f"(c[3])
        : "r"(a[0]), "r"(a[1]), "r"(a[2]), "r"(a[3]), "r"(b0), "r"(b1));
}

// ---------------------------------------------------------------------------
// Kernel 0: dtype probe on scales (true values in (0.001, 0.011]).
// ---------------------------------------------------------------------------
__global__ void detect_kernel(const void* scales) {
    const unsigned short* su = (const unsigned short*)scales;
    int c16 = 0, cbf = 0;
    for (int i = 0; i < 64; i++) {
        float vh = dec_h(su[i]); if (vh > 0.0005f && vh < 0.02f) c16++;
        float vb = dec_b(su[i]); if (vb > 0.0005f && vb < 0.02f) cbf++;
    }
    g_mode = (c16 >= 48) ? 1 : ((cbf >= 48) ? 2 : 0);
}

// ---------------------------------------------------------------------------
// Kernel 1: canonicalize x -> fp16 g_X (8 elems/thread)
// ---------------------------------------------------------------------------
__global__ void convert_x_kernel(const void* __restrict__ x_raw) {
    const int mode = g_mode;
    const size_t i8 = (size_t)blockIdx.x * blockDim.x + threadIdx.x;
    __half out[8];
    if (mode == 0) {
        const float4* xf = (const float4*)x_raw;
        const float4 a = xf[i8 * 2 + 0];
        const float4 b = xf[i8 * 2 + 1];
        out[0] = __float2half(a.x); out[1] = __float2half(a.y);
        out[2] = __float2half(a.z); out[3] = __float2half(a.w);
        out[4] = __float2half(b.x); out[5] = __float2half(b.y);
        out[6] = __float2half(b.z); out[7] = __float2half(b.w);
    } else {
        const uint4 v = ((const uint4*)x_raw)[i8];
        const unsigned int w[4] = {v.x, v.y, v.z, v.w};
        if (mode == 1) {
            *reinterpret_cast<uint4*>(out) = v;
        } else {
#pragma unroll
            for (int k = 0; k < 4; k++) {
                out[2*k+0] = __float2half(dec_b((unsigned short)(w[k] & 0xFFFF)));
                out[2*k+1] = __float2half(dec_b((unsigned short)(w[k] >> 16)));
            }
        }
    }
    *reinterpret_cast<uint4*>(&g_X[i8 * 8]) = *reinterpret_cast<const uint4*>(out);
}

// ---------------------------------------------------------------------------
// Kernel 2: dequantize 4-bit weights -> fp16 W^T [N, K] (K-major, coalesced)
// ---------------------------------------------------------------------------
__global__ void dequant_kernel(const int32_t* __restrict__ qweight,
                               const int32_t* __restrict__ qzeros,
                               const void* __restrict__ scales_raw) {
    const int mode = g_mode;
    const int tx = threadIdx.x;                  // 0..31
    const int ty = threadIdx.y;                  // 0..7
    const int j  = blockIdx.x * 8 + ty;          // N index
    const int i8 = blockIdx.y * 32 + tx;         // K/8 index
    const int g  = i8 >> 4;

    const uint32_t q = (uint32_t)qweight[(size_t)i8 * OUT_F + j];
    const int z = ((uint32_t)qzeros[(size_t)g * (OUT_F >> 3) + (j >> 3)] >> ((j & 7) << 2)) & 0xF;

    float s;
    if (mode == 0)      s = ((const float*)scales_raw)[(size_t)g * OUT_F + j];
    else if (mode == 1) s = dec_h(((const unsigned short*)scales_raw)[(size_t)g * OUT_F + j]);
    else                s = dec_b(((const unsigned short*)scales_raw)[(size_t)g * OUT_F + j]);
    const float zs = s * (float)z;

    __half out8[8];
#pragma unroll
    for (int r = 0; r < 8; r++) {
        const int w = (q >> (r << 2)) & 0xF;
        out8[r] = __float2half(s * (float)w - zs);
    }
    *reinterpret_cast<uint4*>(&g_Wt[(size_t)j * IN_F + i8 * 8]) =
        *reinterpret_cast<const uint4*>(out8);
}

// ---------------------------------------------------------------------------
// Kernel 3: GEMM via mma.sync.m16n8k16 + ldmatrix + 3-stage cp.async.
// CTA 128x128x64, 8 warps (2x4), warp tile 64x32, 2 CTAs/SM (occupancy).
// ---------------------------------------------------------------------------
__global__ void __launch_bounds__(256, 2)
gemm_kernel(const void* __restrict__ bias_raw, void* __restrict__ out_raw) {
    extern __shared__ __align__(128) unsigned char smem[];
    const uint32_t sbase = (uint32_t)__cvta_generic_to_shared(smem);

    const int tid  = threadIdx.x;
    const int wid  = tid >> 5;
    const int lane = tid & 31;
    const int wm   = wid >> 2;            // 0..1 (64-row stripe)
    const int wn   = wid & 3;             // 0..3 (32-col stripe)
    const int mode = g_mode;

    const int m0 = blockIdx.x * BM;
    const int n0 = blockIdx.y * BN;

    // ---- cp.async addressing: one base pointer + constant offsets ----
    // A tile: 128 rows x 8 segs(16B) = 1024 chunks, 4/thread (rows step 32/t)
    // B tile: same shape.
    const int arow = tid >> 3, aseg = tid & 7;
    const __half* gAbase = g_X  + (size_t)(m0 + arow) * IN_F + aseg * 8;
    const __half* gBbase = g_Wt + (size_t)(n0 + arow) * IN_F + aseg * 8;
    const uint32_t sAo = (uint32_t)(arow * LDR2 + aseg * 16);
    const uint32_t sBo = (uint32_t)(A_BYTES + arow * LDR2 + aseg * 16);
    uint32_t koff = 0;   // element offset along K, advances BK per stage

#define LOAD_STAGE(buf_)                                                      \
    do {                                                                      \
        const uint32_t sb_ = sbase + (buf_) * STAGE_BYTES;                    \
        _Pragma("unroll")                                                     \
        for (int t = 0; t < 4; t++)                                           \
            cp16(sb_ + sAo + t * (32 * LDR2), gAbase + koff + t * (32 * IN_F)); \
        _Pragma("unroll")                                                     \
        for (int t = 0; t < 4; t++)                                           \
            cp16(sb_ + sBo + t * (32 * LDR2), gBbase + koff + t * (32 * IN_F)); \
        cp_commit();                                                          \
        koff += BK;                                                           \
    } while (0)

    // ldmatrix per-lane base offsets (within a stage)
    const int l15  = lane & 15;
    const int lsel = (lane >> 4) * 16;
    const uint32_t a_off = (uint32_t)(wm * 64 + l15) * LDR2 + lsel;
    const uint32_t b_off = (uint32_t)A_BYTES + (uint32_t)(wn * 32 + l15) * LDR2 + lsel;

    float acc[4][4][4];
#pragma unroll
    for (int i = 0; i < 4; i++)
#pragma unroll
        for (int j = 0; j < 4; j++)
#pragma unroll
            for (int k = 0; k < 4; k++) acc[i][j][k] = 0.0f;

    // prologue: stages 0,1
    LOAD_STAGE(0);
    LOAD_STAGE(1);

    for (int i = 0; i < NSTG; i++) {
        const int buf = i % STAGES;
        if (i == NSTG - 1) cp_wait<0>(); else cp_wait<1>();
        __syncthreads();

        const int ls = i + STAGES - 1;
        if (ls < NSTG) LOAD_STAGE(ls % STAGES);

        const uint32_t st = sbase + buf * STAGE_BYTES;
#pragma unroll
        for (int kk = 0; kk < BK / 16; kk++) {
            uint32_t af[4][4], bf[2][4];
#pragma unroll
            for (int mi = 0; mi < 4; mi++)
                ldsm4(af[mi], st + a_off + mi * (16 * LDR2) + kk * 32);
#pragma unroll
            for (int nj = 0; nj < 2; nj++)
                ldsm4(bf[nj], st + b_off + nj * (16 * LDR2) + kk * 32);
#pragma unroll
            for (int mi = 0; mi < 4; mi++)
#pragma unroll
                for (int nj = 0; nj < 2; nj++) {
                    mma16816(acc[mi][nj * 2 + 0], af[mi], bf[nj][0], bf[nj][2]);
                    mma16816(acc[mi][nj * 2 + 1], af[mi], bf[nj][1], bf[nj][3]);
                }
        }
    }
#undef LOAD_STAGE

    // ---- epilogue: direct register -> global with fused bias ----
    const int mrow = m0 + wm * 64 + (lane >> 2);
    const int ncol = n0 + wn * 32 + (lane & 3) * 2;

    float bl[4], bh[4];
#pragma unroll
    for (int j = 0; j < 4; j++) {
        const int c = ncol + j * 8;
        if (mode == 0) {
            bl[j] = ((const float*)bias_raw)[c];
            bh[j] = ((const float*)bias_raw)[c + 1];
        } else if (mode == 1) {
            bl[j] = dec_h(((const unsigned short*)bias_raw)[c]);
            bh[j] = dec_h(((const unsigned short*)bias_raw)[c + 1]);
        } else {
            bl[j] = dec_b(((const unsigned short*)bias_raw)[c]);
            bh[j] = dec_b(((const unsigned short*)bias_raw)[c + 1]);
        }
    }

#pragma unroll
    for (int mi = 0; mi < 4; mi++) {
        const int r0 = mrow + mi * 16;
#pragma unroll
        for (int j = 0; j < 4; j++) {
            const int c = ncol + j * 8;
            const float v0 = acc[mi][j][0] + bl[j];
            const float v1 = acc[mi][j][1] + bh[j];
            const float v2 = acc[mi][j][2] + bl[j];
            const float v3 = acc[mi][j][3] + bh[j];
            if (mode == 0) {
                float2 p0, p1;
                p0.x = __half2float(__float2half(v0));
                p0.y = __half2float(__float2half(v1));
                p1.x = __half2float(__float2half(v2));
                p1.y = __half2float(__float2half(v3));
                *reinterpret_cast<float2*>((float*)out_raw + (size_t)r0 * OUT_F + c) = p0;
                *reinterpret_cast<float2*>((float*)out_raw + (size_t)(r0 + 8) * OUT_F + c) = p1;
            } else if (mode == 1) {
                uint32_t p0 = (uint32_t)enc_h(v0) | ((uint32_t)enc_h(v1) << 16);
                uint32_t p1 = (uint32_t)enc_h(v2) | ((uint32_t)enc_h(v3) << 16);
                *reinterpret_cast<uint32_t*>((unsigned short*)out_raw + (size_t)r0 * OUT_F + c) = p0;
                *reinterpret_cast<uint32_t*>((unsigned short*)out_raw + (size_t)(r0 + 8) * OUT_F + c) = p1;
            } else {
                uint32_t p0 = (uint32_t)enc_b(v0) | ((uint32_t)enc_b(v1) << 16);
                uint32_t p1 = (uint32_t)enc_b(v2) | ((uint32_t)enc_b(v3) << 16);
                *reinterpret_cast<uint32_t*>((unsigned short*)out_raw + (size_t)r0 * OUT_F + c) = p0;
                *reinterpret_cast<uint32_t*>((unsigned short*)out_raw + (size_t)(r0 + 8) * OUT_F + c) = p1;
            }
        }
    }
}

// ---------------------------------------------------------------------------
// Launch
// ---------------------------------------------------------------------------
extern "C" void kernel_launch(void* const* d_in, const int* in_sizes, int n_in,
                              void* d_out, int out_size) {
    const void*    x       = d_in[0];
    const int32_t* qweight = (const int32_t*)d_in[1];
    const int32_t* qzeros  = (const int32_t*)d_in[2];
    const void*    scales  = d_in[3];
    const void*    bias    = d_in[4];

    detect_kernel<<<1, 1>>>(scales);

    const unsigned nchunks = (unsigned)((size_t)M_TOTAL * IN_F / 8);
    convert_x_kernel<<<nchunks / 256, 256>>>(x);

    dequant_kernel<<<dim3(OUT_F / 8, IN_F / 256), dim3(32, 8)>>>(qweight, qzeros, scales);

    cudaFuncSetAttribute(gemm_kernel,
                         cudaFuncAttributeMaxDynamicSharedMemorySize, SMEM_TOTAL);
    dim3 grid(M_TOTAL / BM, OUT_F / BN);    // (64, 32)
    gemm_kernel<<<grid, 256, SMEM_TOTAL>>>(bias, d_out);
}

// round 8
// speedup vs baseline: 1.0462x; 1.0246x over previous
#include <cuda_runtime.h>
#include <cuda_fp16.h>
#include <cuda_bf16.h>
#include <cstdint>

// ---------------------------------------------------------------------------
// Problem constants
// ---------------------------------------------------------------------------
constexpr int IN_F    = 4096;    // K
constexpr int OUT_F   = 4096;    // N
constexpr int M_TOTAL = 8192;    // M

// GEMM tiling: CTA 128x128x64, 4 warps (2x2), warp tile 64x64, 3 CTAs/SM
constexpr int BM = 128, BN = 128, BK = 64;
constexpr int STAGES = 2;
constexpr int NSTG   = IN_F / BK;        // 64
constexpr int LDR    = 72;               // smem row stride in halfs (144B)
constexpr int LDR2   = LDR * 2;          // bytes
constexpr int A_BYTES     = BM * LDR2;               // 18432
constexpr int B_BYTES     = BN * LDR2;               // 18432
constexpr int STAGE_BYTES = A_BYTES + B_BYTES;       // 36864
constexpr int SMEM_TOTAL  = STAGES * STAGE_BYTES;    // 73728 per CTA

// Scratch (__device__ globals = allowed scratch)
__device__ __half g_X [(size_t)M_TOTAL * IN_F];   // canonical fp16 x  (64MB)
__device__ __half g_Wt[(size_t)OUT_F * IN_F];     // dequant W^T [N,K] (32MB)
__device__ int    g_mode;                         // 0=f32, 1=fp16, 2=bf16 buffers

// ---------------------------------------------------------------------------
// helpers
// ---------------------------------------------------------------------------
__device__ __forceinline__ float dec_h(unsigned short v) {
    __half_raw h; h.x = v; return __half2float(__half(h));
}
__device__ __forceinline__ float dec_b(unsigned short v) {
    __nv_bfloat16_raw r; r.x = v; return __bfloat162float(__nv_bfloat16(r));
}
__device__ __forceinline__ unsigned short enc_h(float f) {
    __half h = __float2half(f); return reinterpret_cast<unsigned short&>(h);
}
__device__ __forceinline__ unsigned short enc_b(float f) {
    __nv_bfloat16 b = __float2bfloat16(f); return reinterpret_cast<unsigned short&>(b);
}
__device__ __forceinline__ void cp16(uint32_t saddr, const void* g) {
    asm volatile("cp.async.cg.shared.global [%0], [%1], 16;\n" :: "r"(saddr), "l"(g));
}
__device__ __forceinline__ void cp_commit() {
    asm volatile("cp.async.commit_group;\n" ::: "memory");
}
template <int N>
__device__ __forceinline__ void cp_wait() {
    asm volatile("cp.async.wait_group %0;\n" :: "n"(N) : "memory");
}
__device__ __forceinline__ void ldsm4(uint32_t* r, uint32_t addr) {
    asm volatile("ldmatrix.sync.aligned.m8n8.x4.shared.b16 {%0,%1,%2,%3}, [%4];\n"
                 : "=r"(r[0]), "=r"(r[1]), "=r"(r[2]), "=r"(r[3]) : "r"(addr));
}
__device__ __forceinline__ void mma16816(float* c, const uint32_t* a,
                                         uint32_t b0, uint32_t b1) {
    asm volatile(
        "mma.sync.aligned.m16n8k16.row.col.f32.f16.f16.f32 "
        "{%0,%1,%2,%3}, {%4,%5,%6,%7}, {%8,%9}, {%0,%1,%2,%3};\n"
        : "+f"(c[0]), "+f"(c[1]), "+f"(c[2]), "+f"(c[3])
        : "r"(a[0]), "r"(a[1]), "r"(a[2]), "r"(a[3]), "r"(b0), "r"(b1));
}

// ---------------------------------------------------------------------------
// Kernel 0: dtype probe on scales (true values in (0.001, 0.011]).
// ---------------------------------------------------------------------------
__global__ void detect_kernel(const void* scales) {
    const unsigned short* su = (const unsigned short*)scales;
    int c16 = 0, cbf = 0;
    for (int i = 0; i < 64; i++) {
        float vh = dec_h(su[i]); if (vh > 0.0005f && vh < 0.02f) c16++;
        float vb = dec_b(su[i]); if (vb > 0.0005f && vb < 0.02f) cbf++;
    }
    g_mode = (c16 >= 48) ? 1 : ((cbf >= 48) ? 2 : 0);
}

// ---------------------------------------------------------------------------
// Kernel 1: canonicalize x -> fp16 g_X (8 elems/thread)
// ---------------------------------------------------------------------------
__global__ void convert_x_kernel(const void* __restrict__ x_raw) {
    const int mode = g_mode;
    const size_t i8 = (size_t)blockIdx.x * blockDim.x + threadIdx.x;
    __half out[8];
    if (mode == 0) {
        const float4* xf = (const float4*)x_raw;
        const float4 a = xf[i8 * 2 + 0];
        const float4 b = xf[i8 * 2 + 1];
        out[0] = __float2half(a.x); out[1] = __float2half(a.y);
        out[2] = __float2half(a.z); out[3] = __float2half(a.w);
        out[4] = __float2half(b.x); out[5] = __float2half(b.y);
        out[6] = __float2half(b.z); out[7] = __float2half(b.w);
    } else {
        const uint4 v = ((const uint4*)x_raw)[i8];
        const unsigned int w[4] = {v.x, v.y, v.z, v.w};
        if (mode == 1) {
            *reinterpret_cast<uint4*>(out) = v;
        } else {
#pragma unroll
            for (int k = 0; k < 4; k++) {
                out[2*k+0] = __float2half(dec_b((unsigned short)(w[k] & 0xFFFF)));
                out[2*k+1] = __float2half(dec_b((unsigned short)(w[k] >> 16)));
            }
        }
    }
    *reinterpret_cast<uint4*>(&g_X[i8 * 8]) = *reinterpret_cast<const uint4*>(out);
}

// ---------------------------------------------------------------------------
// Kernel 2: dequantize 4-bit weights -> fp16 W^T [N, K] (K-major, coalesced)
// ---------------------------------------------------------------------------
__global__ void dequant_kernel(const int32_t* __restrict__ qweight,
                               const int32_t* __restrict__ qzeros,
                               const void* __restrict__ scales_raw) {
    const int mode = g_mode;
    const int tx = threadIdx.x;                  // 0..31
    const int ty = threadIdx.y;                  // 0..7
    const int j  = blockIdx.x * 8 + ty;          // N index
    const int i8 = blockIdx.y * 32 + tx;         // K/8 index
    const int g  = i8 >> 4;

    const uint32_t q = (uint32_t)qweight[(size_t)i8 * OUT_F + j];
    const int z = ((uint32_t)qzeros[(size_t)g * (OUT_F >> 3) + (j >> 3)] >> ((j & 7) << 2)) & 0xF;

    float s;
    if (mode == 0)      s = ((const float*)scales_raw)[(size_t)g * OUT_F + j];
    else if (mode == 1) s = dec_h(((const unsigned short*)scales_raw)[(size_t)g * OUT_F + j]);
    else                s = dec_b(((const unsigned short*)scales_raw)[(size_t)g * OUT_F + j]);
    const float zs = s * (float)z;

    __half out8[8];
#pragma unroll
    for (int r = 0; r < 8; r++) {
        const int w = (q >> (r << 2)) & 0xF;
        out8[r] = __float2half(s * (float)w - zs);
    }
    *reinterpret_cast<uint4*>(&g_Wt[(size_t)j * IN_F + i8 * 8]) =
        *reinterpret_cast<const uint4*>(out8);
}

// ---------------------------------------------------------------------------
// Kernel 3: GEMM via mma.sync.m16n8k16 + ldmatrix + 2-stage cp.async.
// CTA 128x128x64, 4 warps (2x2), warp tile 64x64, 3 CTAs/SM.
// Pipeline: iter i: wait(stage i), sync, issue load(i+1), compute(i).
// ---------------------------------------------------------------------------
__global__ void __launch_bounds__(128, 3)
gemm_kernel(const void* __restrict__ bias_raw, void* __restrict__ out_raw) {
    extern __shared__ __align__(128) unsigned char smem[];
    const uint32_t sbase = (uint32_t)__cvta_generic_to_shared(smem);

    const int tid  = threadIdx.x;     // 0..127
    const int wid  = tid >> 5;        // 0..3
    const int lane = tid & 31;
    const int wm   = wid >> 1;        // 0..1 (64-row stripe)
    const int wn   = wid & 1;         // 0..1 (64-col stripe)
    const int mode = g_mode;

    const int m0 = blockIdx.x * BM;
    const int n0 = blockIdx.y * BN;

    // cp.async addressing: thread covers rows (tid>>3) + t*16, seg (tid&7)
    const int arow = tid >> 3, aseg = tid & 7;
    const __half* gAbase = g_X  + (size_t)(m0 + arow) * IN_F + aseg * 8;
    const __half* gBbase = g_Wt + (size_t)(n0 + arow) * IN_F + aseg * 8;
    const uint32_t sAo = (uint32_t)(arow * LDR2 + aseg * 16);
    const uint32_t sBo = (uint32_t)(A_BYTES + arow * LDR2 + aseg * 16);
    uint32_t koff = 0;

#define LOAD_STAGE(buf_)                                                        \
    do {                                                                        \
        const uint32_t sb_ = sbase + (buf_) * STAGE_BYTES;                      \
        _Pragma("unroll")                                                       \
        for (int t = 0; t < 8; t++)                                             \
            cp16(sb_ + sAo + t * (16 * LDR2), gAbase + koff + t * (16 * IN_F)); \
        _Pragma("unroll")                                                       \
        for (int t = 0; t < 8; t++)                                             \
            cp16(sb_ + sBo + t * (16 * LDR2), gBbase + koff + t * (16 * IN_F)); \
        cp_commit();                                                            \
        koff += BK;                                                             \
    } while (0)

    // ldmatrix per-lane base offsets (within a stage)
    const int l15  = lane & 15;
    const int lsel = (lane >> 4) * 16;
    const uint32_t a_off = (uint32_t)(wm * 64 + l15) * LDR2 + lsel;
    const uint32_t b_off = (uint32_t)A_BYTES + (uint32_t)(wn * 64 + l15) * LDR2 + lsel;

    float acc[4][8][4];
#pragma unroll
    for (int i = 0; i < 4; i++)
#pragma unroll
        for (int j = 0; j < 8; j++)
#pragma unroll
            for (int k = 0; k < 4; k++) acc[i][j][k] = 0.0f;

    // prologue: stage 0
    LOAD_STAGE(0);

    for (int i = 0; i < NSTG; i++) {
        const int buf = i & 1;
        cp_wait<0>();          // stage i resident (stage i+1 not yet issued)
        __syncthreads();       // all warps see stage i; prev compute on buf^1 done

        if (i + 1 < NSTG) LOAD_STAGE(buf ^ 1);   // overlaps compute below

        const uint32_t st = sbase + buf * STAGE_BYTES;
#pragma unroll
        for (int kk = 0; kk < BK / 16; kk++) {
            uint32_t bf[4][4];
#pragma unroll
            for (int nj = 0; nj < 4; nj++)
                ldsm4(bf[nj], st + b_off + nj * (16 * LDR2) + kk * 32);
#pragma unroll
            for (int mi = 0; mi < 4; mi++) {
                uint32_t af[4];
                ldsm4(af, st + a_off + mi * (16 * LDR2) + kk * 32);
#pragma unroll
                for (int nj = 0; nj < 4; nj++) {
                    mma16816(acc[mi][nj * 2 + 0], af, bf[nj][0], bf[nj][2]);
                    mma16816(acc[mi][nj * 2 + 1], af, bf[nj][1], bf[nj][3]);
                }
            }
        }
    }
#undef LOAD_STAGE

    // ---- epilogue: direct register -> global with fused bias ----
    const int mrow = m0 + wm * 64 + (lane >> 2);
    const int ncol = n0 + wn * 64 + (lane & 3) * 2;

    float bl[8], bh[8];
#pragma unroll
    for (int j = 0; j < 8; j++) {
        const int c = ncol + j * 8;
        if (mode == 0) {
            bl[j] = ((const float*)bias_raw)[c];
            bh[j] = ((const float*)bias_raw)[c + 1];
        } else if (mode == 1) {
            bl[j] = dec_h(((const unsigned short*)bias_raw)[c]);
            bh[j] = dec_h(((const unsigned short*)bias_raw)[c + 1]);
        } else {
            bl[j] = dec_b(((const unsigned short*)bias_raw)[c]);
            bh[j] = dec_b(((const unsigned short*)bias_raw)[c + 1]);
        }
    }

#pragma unroll
    for (int mi = 0; mi < 4; mi++) {
        const int r0 = mrow + mi * 16;
#pragma unroll
        for (int j = 0; j < 8; j++) {
            const int c = ncol + j * 8;
            const float v0 = acc[mi][j][0] + bl[j];
            const float v1 = acc[mi][j][1] + bh[j];
            const float v2 = acc[mi][j][2] + bl[j];
            const float v3 = acc[mi][j][3] + bh[j];
            if (mode == 0) {
                float2 p0, p1;
                p0.x = __half2float(__float2half(v0));
                p0.y = __half2float(__float2half(v1));
                p1.x = __half2float(__float2half(v2));
                p1.y = __half2float(__float2half(v3));
                *reinterpret_cast<float2*>((float*)out_raw + (size_t)r0 * OUT_F + c) = p0;
                *reinterpret_cast<float2*>((float*)out_raw + (size_t)(r0 + 8) * OUT_F + c) = p1;
            } else if (mode == 1) {
                uint32_t p0 = (uint32_t)enc_h(v0) | ((uint32_t)enc_h(v1) << 16);
                uint32_t p1 = (uint32_t)enc_h(v2) | ((uint32_t)enc_h(v3) << 16);
                *reinterpret_cast<uint32_t*>((unsigned short*)out_raw + (size_t)r0 * OUT_F + c) = p0;
                *reinterpret_cast<uint32_t*>((unsigned short*)out_raw + (size_t)(r0 + 8) * OUT_F + c) = p1;
            } else {
                uint32_t p0 = (uint32_t)enc_b(v0) | ((uint32_t)enc_b(v1) << 16);
                uint32_t p1 = (uint32_t)enc_b(v2) | ((uint32_t)enc_b(v3) << 16);
                *reinterpret_cast<uint32_t*>((unsigned short*)out_raw + (size_t)r0 * OUT_F + c) = p0;
                *reinterpret_cast<uint32_t*>((unsigned short*)out_raw + (size_t)(r0 + 8) * OUT_F + c) = p1;
            }
        }
    }
}

// ---------------------------------------------------------------------------
// Launch
// ---------------------------------------------------------------------------
extern "C" void kernel_launch(void* const* d_in, const int* in_sizes, int n_in,
                              void* d_out, int out_size) {
    const void*    x       = d_in[0];
    const int32_t* qweight = (const int32_t*)d_in[1];
    const int32_t* qzeros  = (const int32_t*)d_in[2];
    const void*    scales  = d_in[3];
    const void*    bias    = d_in[4];

    detect_kernel<<<1, 1>>>(scales);

    const unsigned nchunks = (unsigned)((size_t)M_TOTAL * IN_F / 8);
    convert_x_kernel<<<nchunks / 256, 256>>>(x);

    dequant_kernel<<<dim3(OUT_F / 8, IN_F / 256), dim3(32, 8)>>>(qweight, qzeros, scales);

    cudaFuncSetAttribute(gemm_kernel,
                         cudaFuncAttributeMaxDynamicSharedMemorySize, SMEM_TOTAL);
    dim3 grid(M_TOTAL / BM, OUT_F / BN);    // (64, 32)
    gemm_kernel<<<grid, 128, SMEM_TOTAL>>>(bias, d_out);
}

// round 10
// speedup vs baseline: 1.0542x; 1.0077x over previous
#include <cuda_runtime.h>
#include <cuda_fp16.h>
#include <cuda_bf16.h>
#include <cstdint>

// ---------------------------------------------------------------------------
// Problem constants
// ---------------------------------------------------------------------------
constexpr int IN_F    = 4096;    // K
constexpr int OUT_F   = 4096;    // N
constexpr int M_TOTAL = 8192;    // M

// GEMM tiling: CTA 128x128x64. 4 consumer warps (2x2, warp tile 64x64) +
// 2 producer warps (cp.async). 3-stage mbarrier ring. 2 CTAs/SM.
constexpr int BM = 128, BN = 128, BK = 64;
constexpr int STAGES = 3;
constexpr int NSTG   = IN_F / BK;        // 64
constexpr int LDR    = 72;               // smem row stride in halfs (144B)
constexpr int LDR2   = LDR * 2;          // bytes
constexpr int A_BYTES     = BM * LDR2;               // 18432
constexpr int B_BYTES     = BN * LDR2;               // 18432
constexpr int STAGE_BYTES = A_BYTES + B_BYTES;       // 36864

constexpr int SM_FULL   = 0;      // 3 x 8B full mbarriers
constexpr int SM_EMPTY  = 32;     // 3 x 8B empty mbarriers
constexpr int SM_STAGE0 = 1024;
constexpr int SMEM_TOTAL = SM_STAGE0 + STAGES * STAGE_BYTES;   // 111616

constexpr int N_PROD_THREADS = 64;    // 2 warps
constexpr int N_CONS_THREADS = 128;   // 4 warps
constexpr int THREADS = N_PROD_THREADS + N_CONS_THREADS;       // 192

// Scratch (__device__ globals = allowed scratch)
__device__ __half g_X [(size_t)M_TOTAL * IN_F];   // canonical fp16 x  (64MB)
__device__ __half g_Wt[(size_t)OUT_F * IN_F];     // dequant W^T [N,K] (32MB)
__device__ int    g_mode;                         // 0=f32, 1=fp16, 2=bf16 buffers

// ---------------------------------------------------------------------------
// helpers
// ---------------------------------------------------------------------------
__device__ __forceinline__ float dec_h(unsigned short v) {
    __half_raw h; h.x = v; return __half2float(__half(h));
}
__device__ __forceinline__ float dec_b(unsigned short v) {
    __nv_bfloat16_raw r; r.x = v; return __bfloat162float(__nv_bfloat16(r));
}
__device__ __forceinline__ unsigned short enc_h(float f) {
    __half h = __float2half(f); return reinterpret_cast<unsigned short&>(h);
}
__device__ __forceinline__ unsigned short enc_b(float f) {
    __nv_bfloat16 b = __float2bfloat16(f); return reinterpret_cast<unsigned short&>(b);
}
__device__ __forceinline__ void cp16(uint32_t saddr, const void* g) {
    asm volatile("cp.async.cg.shared.global [%0], [%1], 16;\n" :: "r"(saddr), "l"(g));
}
__device__ __forceinline__ void ldsm4(uint32_t* r, uint32_t addr) {
    asm volatile("ldmatrix.sync.aligned.m8n8.x4.shared.b16 {%0,%1,%2,%3}, [%4];\n"
                 : "=r"(r[0]), "=r"(r[1]), "=r"(r[2]), "=r"(r[3]) : "r"(addr));
}
__device__ __forceinline__ void mma16816(float* c, const uint32_t* a,
                                         uint32_t b0, uint32_t b1) {
    asm volatile(
        "mma.sync.aligned.m16n8k16.row.col.f32.f16.f16.f32 "
        "{%0,%1,%2,%3}, {%4,%5,%6,%7}, {%8,%9}, {%0,%1,%2,%3};\n"
        : "+f"(c[0]), "+f"(c[1]), "+f"(c[2]), "+f"(c[3])
        : "r"(a[0]), "r"(a[1]), "r"(a[2]), "r"(a[3]), "r"(b0), "r"(b1));
}
__device__ __forceinline__ void mbar_init(uint32_t a, uint32_t cnt) {
    asm volatile("mbarrier.init.shared.b64 [%0], %1;\n" :: "r"(a), "r"(cnt) : "memory");
}
__device__ __forceinline__ void mbar_arrive(uint32_t a) {
    asm volatile("mbarrier.arrive.shared.b64 _, [%0];\n" :: "r"(a) : "memory");
}
// Arrive on mbar once all of this thread's prior cp.asyncs have completed.
// .noinc is REQUIRED: the default form bumps the expected-arrival count and
// deadlocks a barrier initialized with a fixed thread count (round-9 hang).
__device__ __forceinline__ void cp_async_mbar_arrive(uint32_t a) {
    asm volatile("cp.async.mbarrier.arrive.noinc.shared.b64 [%0];\n" :: "r"(a) : "memory");
}
__device__ __forceinline__ void mbar_wait(uint32_t a, uint32_t parity) {
    uint32_t done;
    asm volatile("{\n\t.reg .pred p;\n\t"
        "mbarrier.try_wait.parity.acquire.cta.shared::cta.b64 p, [%1], %2;\n\t"
        "selp.b32 %0, 1, 0, p;\n\t}" : "=r"(done) : "r"(a), "r"(parity) : "memory");
    if (!done) {
        asm volatile("{\n\t.reg .pred P1;\n\t"
            "W%=:\n\t"
            "mbarrier.try_wait.parity.acquire.cta.shared::cta.b64 P1, [%0], %1, 0x989680;\n\t"
            "@P1 bra.uni D%=;\n\t"
            "bra.uni W%=;\n\t"
            "D%=:\n\t}" :: "r"(a), "r"(parity) : "memory");
    }
}

// ---------------------------------------------------------------------------
// Kernel 0: dtype probe on scales (true values in (0.001, 0.011]).
// ---------------------------------------------------------------------------
__global__ void detect_kernel(const void* scales) {
    const unsigned short* su = (const unsigned short*)scales;
    int c16 = 0, cbf = 0;
    for (int i = 0; i < 64; i++) {
        float vh = dec_h(su[i]); if (vh > 0.0005f && vh < 0.02f) c16++;
        float vb = dec_b(su[i]); if (vb > 0.0005f && vb < 0.02f) cbf++;
    }
    g_mode = (c16 >= 48) ? 1 : ((cbf >= 48) ? 2 : 0);
}

// ---------------------------------------------------------------------------
// Kernel 1: canonicalize x -> fp16 g_X (8 elems/thread)
// ---------------------------------------------------------------------------
__global__ void convert_x_kernel(const void* __restrict__ x_raw) {
    const int mode = g_mode;
    const size_t i8 = (size_t)blockIdx.x * blockDim.x + threadIdx.x;
    __half out[8];
    if (mode == 0) {
        const float4* xf = (const float4*)x_raw;
        const float4 a = xf[i8 * 2 + 0];
        const float4 b = xf[i8 * 2 + 1];
        out[0] = __float2half(a.x); out[1] = __float2half(a.y);
        out[2] = __float2half(a.z); out[3] = __float2half(a.w);
        out[4] = __float2half(b.x); out[5] = __float2half(b.y);
        out[6] = __float2half(b.z); out[7] = __float2half(b.w);
    } else {
        const uint4 v = ((const uint4*)x_raw)[i8];
        const unsigned int w[4] = {v.x, v.y, v.z, v.w};
        if (mode == 1) {
            *reinterpret_cast<uint4*>(out) = v;
        } else {
#pragma unroll
            for (int k = 0; k < 4; k++) {
                out[2*k+0] = __float2half(dec_b((unsigned short)(w[k] & 0xFFFF)));
                out[2*k+1] = __float2half(dec_b((unsigned short)(w[k] >> 16)));
            }
        }
    }
    *reinterpret_cast<uint4*>(&g_X[i8 * 8]) = *reinterpret_cast<const uint4*>(out);
}

// ---------------------------------------------------------------------------
// Kernel 2: dequantize 4-bit weights -> fp16 W^T [N, K] (K-major, coalesced)
// ---------------------------------------------------------------------------
__global__ void dequant_kernel(const int32_t* __restrict__ qweight,
                               const int32_t* __restrict__ qzeros,
                               const void* __restrict__ scales_raw) {
    const int mode = g_mode;
    const int tx = threadIdx.x;                  // 0..31
    const int ty = threadIdx.y;                  // 0..7
    const int j  = blockIdx.x * 8 + ty;          // N index
    const int i8 = blockIdx.y * 32 + tx;         // K/8 index
    const int g  = i8 >> 4;

    const uint32_t q = (uint32_t)qweight[(size_t)i8 * OUT_F + j];
    const int z = ((uint32_t)qzeros[(size_t)g * (OUT_F >> 3) + (j >> 3)] >> ((j & 7) << 2)) & 0xF;

    float s;
    if (mode == 0)      s = ((const float*)scales_raw)[(size_t)g * OUT_F + j];
    else if (mode == 1) s = dec_h(((const unsigned short*)scales_raw)[(size_t)g * OUT_F + j]);
    else                s = dec_b(((const unsigned short*)scales_raw)[(size_t)g * OUT_F + j]);
    const float zs = s * (float)z;

    __half out8[8];
#pragma unroll
    for (int r = 0; r < 8; r++) {
        const int w = (q >> (r << 2)) & 0xF;
        out8[r] = __float2half(s * (float)w - zs);
    }
    *reinterpret_cast<uint4*>(&g_Wt[(size_t)j * IN_F + i8 * 8]) =
        *reinterpret_cast<const uint4*>(out8);
}

// ---------------------------------------------------------------------------
// Kernel 3: warp-specialized GEMM.
// Warps 0-3: consumers (ldsm + mma only).  Warps 4-5: producers (cp.async).
// full[s]: producers' cp.asyncs complete (count=64 prod threads, noinc arrive).
// empty[s]: consumers done reading stage (count=128 cons threads).
// ---------------------------------------------------------------------------
__global__ void __launch_bounds__(THREADS, 2)
gemm_kernel(const void* __restrict__ bias_raw, void* __restrict__ out_raw) {
    extern __shared__ __align__(128) unsigned char smem[];
    const uint32_t sbase = (uint32_t)__cvta_generic_to_shared(smem);

    const int tid  = threadIdx.x;     // 0..191
    const int wid  = tid >> 5;        // 0..5
    const int lane = tid & 31;
    const int mode = g_mode;

    const int m0 = blockIdx.x * BM;
    const int n0 = blockIdx.y * BN;

    if (tid == 0) {
#pragma unroll
        for (int s = 0; s < STAGES; s++) {
            mbar_init(sbase + SM_FULL  + s * 8, N_PROD_THREADS);
            mbar_init(sbase + SM_EMPTY + s * 8, N_CONS_THREADS);
        }
    }
    __syncthreads();

    if (wid >= 4) {
        // ---------------- producers (warps 4,5; 64 threads) ----------------
        const int ptid = tid - N_CONS_THREADS;        // 0..63
        const int arow = ptid >> 3, aseg = ptid & 7;
        const __half* gA = g_X  + (size_t)(m0 + arow) * IN_F + aseg * 8;
        const __half* gB = g_Wt + (size_t)(n0 + arow) * IN_F + aseg * 8;
        const uint32_t sAo = (uint32_t)(arow * LDR2 + aseg * 16);
        const uint32_t sBo = (uint32_t)(A_BYTES + arow * LDR2 + aseg * 16);
        uint32_t koff = 0;

        for (int s = 0; s < NSTG; s++) {
            const int buf = s % STAGES;
            const uint32_t parity = 1u ^ (uint32_t)((s / STAGES) & 1);
            mbar_wait(sbase + SM_EMPTY + buf * 8, parity);  // first lap passes
            const uint32_t sb = sbase + SM_STAGE0 + buf * STAGE_BYTES;
#pragma unroll
            for (int t = 0; t < 16; t++)
                cp16(sb + sAo + t * (8 * LDR2), gA + koff + t * (8 * IN_F));
#pragma unroll
            for (int t = 0; t < 16; t++)
                cp16(sb + sBo + t * (8 * LDR2), gB + koff + t * (8 * IN_F));
            cp_async_mbar_arrive(sbase + SM_FULL + buf * 8);
            koff += BK;
        }
        return;   // producers exit; consumers still hold the CTA
    }

    // ------------------- consumers (warps 0-3; 128 threads) ----------------
    const int wm = wid >> 1;          // 0..1 (64-row stripe)
    const int wn = wid & 1;           // 0..1 (64-col stripe)

    const int l15  = lane & 15;
    const int lsel = (lane >> 4) * 16;
    const uint32_t a_off = (uint32_t)(wm * 64 + l15) * LDR2 + lsel;
    const uint32_t b_off = (uint32_t)A_BYTES + (uint32_t)(wn * 64 + l15) * LDR2 + lsel;

    float acc[4][8][4];
#pragma unroll
    for (int i = 0; i < 4; i++)
#pragma unroll
        for (int j = 0; j < 8; j++)
#pragma unroll
            for (int k = 0; k < 4; k++) acc[i][j][k] = 0.0f;

    for (int s = 0; s < NSTG; s++) {
        const int buf = s % STAGES;
        const uint32_t parity = (uint32_t)((s / STAGES) & 1);
        mbar_wait(sbase + SM_FULL + buf * 8, parity);

        const uint32_t st = sbase + SM_STAGE0 + buf * STAGE_BYTES;
#pragma unroll
        for (int kk = 0; kk < BK / 16; kk++) {
            uint32_t bf[4][4];
#pragma unroll
            for (int nj = 0; nj < 4; nj++)
                ldsm4(bf[nj], st + b_off + nj * (16 * LDR2) + kk * 32);
#pragma unroll
            for (int mi = 0; mi < 4; mi++) {
                uint32_t af[4];
                ldsm4(af, st + a_off + mi * (16 * LDR2) + kk * 32);
#pragma unroll
                for (int nj = 0; nj < 4; nj++) {
                    mma16816(acc[mi][nj * 2 + 0], af, bf[nj][0], bf[nj][2]);
                    mma16816(acc[mi][nj * 2 + 1], af, bf[nj][1], bf[nj][3]);
                }
            }
        }
        mbar_arrive(sbase + SM_EMPTY + buf * 8);
    }

    // ---- epilogue: direct register -> global with fused bias ----
    const int mrow = m0 + wm * 64 + (lane >> 2);
    const int ncol = n0 + wn * 64 + (lane & 3) * 2;

    float bl[8], bh[8];
#pragma unroll
    for (int j = 0; j < 8; j++) {
        const int c = ncol + j * 8;
        if (mode == 0) {
            bl[j] = ((const float*)bias_raw)[c];
            bh[j] = ((const float*)bias_raw)[c + 1];
        } else if (mode == 1) {
            bl[j] = dec_h(((const unsigned short*)bias_raw)[c]);
            bh[j] = dec_h(((const unsigned short*)bias_raw)[c + 1]);
        } else {
            bl[j] = dec_b(((const unsigned short*)bias_raw)[c]);
            bh[j] = dec_b(((const unsigned short*)bias_raw)[c + 1]);
        }
    }

#pragma unroll
    for (int mi = 0; mi < 4; mi++) {
        const int r0 = mrow + mi * 16;
#pragma unroll
        for (int j = 0; j < 8; j++) {
            const int c = ncol + j * 8;
            const float v0 = acc[mi][j][0] + bl[j];
            const float v1 = acc[mi][j][1] + bh[j];
            const float v2 = acc[mi][j][2] + bl[j];
            const float v3 = acc[mi][j][3] + bh[j];
            if (mode == 0) {
                float2 p0, p1;
                p0.x = __half2float(__float2half(v0));
                p0.y = __half2float(__float2half(v1));
                p1.x = __half2float(__float2half(v2));
                p1.y = __half2float(__float2half(v3));
                *reinterpret_cast<float2*>((float*)out_raw + (size_t)r0 * OUT_F + c) = p0;
                *reinterpret_cast<float2*>((float*)out_raw + (size_t)(r0 + 8) * OUT_F + c) = p1;
            } else if (mode == 1) {
                uint32_t p0 = (uint32_t)enc_h(v0) | ((uint32_t)enc_h(v1) << 16);
                uint32_t p1 = (uint32_t)enc_h(v2) | ((uint32_t)enc_h(v3) << 16);
                *reinterpret_cast<uint32_t*>((unsigned short*)out_raw + (size_t)r0 * OUT_F + c) = p0;
                *reinterpret_cast<uint32_t*>((unsigned short*)out_raw + (size_t)(r0 + 8) * OUT_F + c) = p1;
            } else {
                uint32_t p0 = (uint32_t)enc_b(v0) | ((uint32_t)enc_b(v1) << 16);
                uint32_t p1 = (uint32_t)enc_b(v2) | ((uint32_t)enc_b(v3) << 16);
                *reinterpret_cast<uint32_t*>((unsigned short*)out_raw + (size_t)r0 * OUT_F + c) = p0;
                *reinterpret_cast<uint32_t*>((unsigned short*)out_raw + (size_t)(r0 + 8) * OUT_F + c) = p1;
            }
        }
    }
}

// ---------------------------------------------------------------------------
// Launch
// ---------------------------------------------------------------------------
extern "C" void kernel_launch(void* const* d_in, const int* in_sizes, int n_in,
                              void* d_out, int out_size) {
    const void*    x       = d_in[0];
    const int32_t* qweight = (const int32_t*)d_in[1];
    const int32_t* qzeros  = (const int32_t*)d_in[2];
    const void*    scales  = d_in[3];
    const void*    bias    = d_in[4];

    detect_kernel<<<1, 1>>>(scales);

    const unsigned nchunks = (unsigned)((size_t)M_TOTAL * IN_F / 8);
    convert_x_kernel<<<nchunks / 256, 256>>>(x);

    dequant_kernel<<<dim3(OUT_F / 8, IN_F / 256), dim3(32, 8)>>>(qweight, qzeros, scales);

    cudaFuncSetAttribute(gemm_kernel,
                         cudaFuncAttributeMaxDynamicSharedMemorySize, SMEM_TOTAL);
    dim3 grid(M_TOTAL / BM, OUT_F / BN);    // (64, 32)
    gemm_kernel<<<grid, THREADS, SMEM_TOTAL>>>(bias, d_out);
}